// round 16
// baseline (speedup 1.0000x reference)
#include <cuda_runtime.h>
#include <cstdint>

#define NFEAT 256
#define NINT  255
#define RPB   16      // rows per block
#define RPW   8       // rows per warp
#define NTHR  64      // 2 warps

__device__ __forceinline__ float ex2f(float v){float y;asm("ex2.approx.ftz.f32 %0,%1;":"=f"(y):"f"(v));return y;}
__device__ __forceinline__ float lg2f(float v){float y;asm("lg2.approx.ftz.f32 %0,%1;":"=f"(y):"f"(v));return y;}
__device__ __forceinline__ float frcp(float v){float y;asm("rcp.approx.ftz.f32 %0,%1;":"=f"(y):"f"(v));return y;}

// w = sigmoid((x-sc) + log((-log u1)/(-log u0))) == b/(b + a*e^{sc-x}),
// a=log2(u0), b=log2(u1) (log base cancels in the ratio). scp = sc*log2(e).
__device__ __forceinline__ float gate_w(float2 uu, float xv, float scp){
    const float LOG2E = 1.4426950408889634f;
    float a = lg2f(fmaxf(uu.x, 1e-10f));
    float b = lg2f(fmaxf(uu.y, 1e-10f));
    float E = ex2f(fmaf(xv, -LOG2E, scp));
    return b * frcp(fmaf(a, E, b));
}

struct URow { float2 u7[4]; float2 u6[2]; float2 u5; float2 uS; };

// streaming (evict-first) loads: u is strictly single-use
__device__ __forceinline__ void load_urow(URow& r, const float2* __restrict__ ub,
                                          int lane, int gs){
    #pragma unroll
    for (int c = 0; c < 4; c++) r.u7[c] = __ldcs(&ub[127 + 32*c + lane]);
    #pragma unroll
    for (int c = 0; c < 2; c++) r.u6[c] = __ldcs(&ub[63 + 32*c + lane]);
    r.u5 = __ldcs(&ub[31 + lane]);
    r.uS = __ldcs(&ub[gs]);
}

__global__ void __launch_bounds__(NTHR, 10)
soft_tree_kernel(const float* __restrict__ x, const float* __restrict__ split_cond,
                 const float* __restrict__ u, const float* __restrict__ leaf_values,
                 const int* __restrict__ split_idx, float* __restrict__ out)
{
    // shared: x tile [RPB][NFEAT], then node const table, then leaf table
    extern __shared__ float smem[];
    float*  xs = smem;                                   // 16 KB
    float2* nc = (float2*)(smem + RPB * NFEAT);          // 256 * 8B  {scp, idx_bits}
    float2* lc = nc + 256;                               // 128 * 8B  {lf0, lfd}

    const unsigned FULL = 0xffffffffu;
    const float LOG2E = 1.4426950408889634f;
    const int tid  = threadIdx.x;
    const int lane = tid & 31;
    const int wid  = tid >> 5;
    const int warp_row0 = blockIdx.x * RPB + wid * RPW;
    float* xw = xs + (wid * RPW) * NFEAT;

    // build per-node constant tables (block-cooperative, once)
    for (int t = tid; t < NINT; t += NTHR)
        nc[t] = make_float2(split_cond[t] * LOG2E, __int_as_float(split_idx[t]));
    for (int t = tid; t < 128; t += NTHR) {
        float2 lf = reinterpret_cast<const float2*>(leaf_values)[t];
        lc[t] = make_float2(lf.x, lf.y - lf.x);
    }

    const int gs = (lane < 31) ? lane : 30;   // small-level node (lane31 dup, unused)
    const float2* ub0 = reinterpret_cast<const float2*>(u + (size_t)warp_row0 * (2*NINT));

    // prefetch u for row 0 BEFORE staging x, so both are in flight together
    URow cur;
    load_urow(cur, ub0, lane, gs);

    // stage this warp's RPW x-rows into shared (coalesced float4, streaming)
    {
        const float4* xg  = reinterpret_cast<const float4*>(x) + (size_t)warp_row0 * (NFEAT/4);
        float4*       xs4 = reinterpret_cast<float4*>(xw);
        #pragma unroll
        for (int i = 0; i < RPW*(NFEAT/4)/32; i++) xs4[i*32+lane] = __ldcs(&xg[i*32+lane]);
    }
    __syncthreads();   // tables + tiles visible

    float myres = 0.0f;

    #pragma unroll
    for (int i = 0; i < RPW; i++) {
        const float* xr = xw + i*NFEAT;

        // ---- issue next row's u loads before touching this row's data ----
        URow nxt;
        if (i + 1 < RPW)
            load_urow(nxt, ub0 + (size_t)(i+1)*NINT, lane, gs);

        // level 7: gate + fold leaves; lane holds v7 of local nodes 32c+lane
        float v7[4];
        #pragma unroll
        for (int c = 0; c < 4; c++) {
            float2 n  = nc[127 + 32*c + lane];
            float  xv = xr[__float_as_int(n.y)];
            float  w  = gate_w(cur.u7[c], xv, n.x);
            float2 lf = lc[32*c + lane];
            v7[c] = fmaf(w, lf.y, lf.x);
        }
        // level 6
        float v6[2];
        #pragma unroll
        for (int c = 0; c < 2; c++) {
            float2 n  = nc[63 + 32*c + lane];
            float  w  = gate_w(cur.u6[c], xr[__float_as_int(n.y)], n.x);
            float xa = __shfl_sync(FULL, v7[2*c],   2*lane);
            float xb = __shfl_sync(FULL, v7[2*c+1], 2*lane);
            float ya = __shfl_sync(FULL, v7[2*c],   2*lane+1);
            float yb = __shfl_sync(FULL, v7[2*c+1], 2*lane+1);
            float vL = (lane < 16) ? xa : xb;
            float vR = (lane < 16) ? ya : yb;
            v6[c] = fmaf(w, vR - vL, vL);
        }
        // level 5 (lane = node)
        float v5;
        {
            float2 n = nc[31 + lane];
            float  w = gate_w(cur.u5, xr[__float_as_int(n.y)], n.x);
            float xa = __shfl_sync(FULL, v6[0], 2*lane);
            float xb = __shfl_sync(FULL, v6[1], 2*lane);
            float ya = __shfl_sync(FULL, v6[0], 2*lane+1);
            float yb = __shfl_sync(FULL, v6[1], 2*lane+1);
            float vL = (lane < 16) ? xa : xb;
            float vR = (lane < 16) ? ya : yb;
            v5 = fmaf(w, vR - vL, vL);
        }
        // levels 4..0: all 31 gates in one warp-wide pass, fold by shuffle
        float ws;
        {
            float2 n = nc[gs];
            ws = gate_w(cur.uS, xr[__float_as_int(n.y)], n.x);  // lane k: node k (k<=30)
        }
        float vL = __shfl_sync(FULL, v5, 2*lane);
        float vR = __shfl_sync(FULL, v5, 2*lane+1);
        float v4 = fmaf(__shfl_sync(FULL, ws, 15+lane), vR-vL, vL);   // lanes<16
        vL = __shfl_sync(FULL, v4, 2*lane);
        vR = __shfl_sync(FULL, v4, 2*lane+1);
        float v3 = fmaf(__shfl_sync(FULL, ws, 7+lane), vR-vL, vL);    // lanes<8
        vL = __shfl_sync(FULL, v3, 2*lane);
        vR = __shfl_sync(FULL, v3, 2*lane+1);
        float v2 = fmaf(__shfl_sync(FULL, ws, 3+lane), vR-vL, vL);    // lanes<4
        vL = __shfl_sync(FULL, v2, 2*lane);
        vR = __shfl_sync(FULL, v2, 2*lane+1);
        float v1 = fmaf(__shfl_sync(FULL, ws, 1+lane), vR-vL, vL);    // lanes<2
        vL = __shfl_sync(FULL, v1, 0);
        vR = __shfl_sync(FULL, v1, 1);
        float v0 = fmaf(__shfl_sync(FULL, ws, 0), vR-vL, vL);         // all lanes equal

        if (lane == i) myres = v0;

        cur = nxt;   // rotate pipeline
    }

    if (lane < RPW) out[warp_row0 + lane] = myres;
}

extern "C" void kernel_launch(void* const* d_in, const int* in_sizes, int n_in,
                              void* d_out, int out_size)
{
    const float* x  = (const float*)d_in[0];
    const float* sc = (const float*)d_in[1];
    const float* u  = (const float*)d_in[2];
    const float* lv = (const float*)d_in[3];
    const int*   si = (const int*)d_in[4];
    float* out = (float*)d_out;

    const size_t smem = (size_t)RPB * NFEAT * sizeof(float)   // 16 KB x tile
                      + 256 * sizeof(float2)                  // node consts
                      + 128 * sizeof(float2);                 // leaf consts
    cudaFuncSetAttribute(soft_tree_kernel,
                         cudaFuncAttributeMaxDynamicSharedMemorySize, (int)smem);
    int blocks = out_size / RPB;                              // 262144/16 = 16384
    soft_tree_kernel<<<blocks, NTHR, smem>>>(x, sc, u, lv, si, out);
}

// round 17
// speedup vs baseline: 1.2843x; 1.2843x over previous
#include <cuda_runtime.h>
#include <cstdint>

#define NFEAT 256
#define NINT  255
#define RPB   32      // rows per block
#define RPW   8       // rows per warp
#define NTHR  128     // 4 warps

__device__ __forceinline__ float ex2f(float v){float y;asm("ex2.approx.ftz.f32 %0,%1;":"=f"(y):"f"(v));return y;}
__device__ __forceinline__ float lg2f(float v){float y;asm("lg2.approx.ftz.f32 %0,%1;":"=f"(y):"f"(v));return y;}
__device__ __forceinline__ float frcp(float v){float y;asm("rcp.approx.ftz.f32 %0,%1;":"=f"(y):"f"(v));return y;}

// w = sigmoid((x-sc) + log((-log u1)/(-log u0))) == b/(b + a*e^{sc-x}),
// a=log2(u0), b=log2(u1) (log base cancels in the ratio). scp = sc*log2(e).
__device__ __forceinline__ float gate_w(float2 uu, float xv, float scp){
    const float LOG2E = 1.4426950408889634f;
    float a = lg2f(fmaxf(uu.x, 1e-10f));
    float b = lg2f(fmaxf(uu.y, 1e-10f));
    float E = ex2f(fmaf(xv, -LOG2E, scp));
    return b * frcp(fmaf(a, E, b));
}

struct URow { float2 u7[4]; float2 u6[2]; float2 u5; float2 uS; };

// streaming (evict-first) loads: u is strictly single-use
__device__ __forceinline__ void load_urow(URow& r, const float2* __restrict__ ub,
                                          int lane, int gs){
    #pragma unroll
    for (int c = 0; c < 4; c++) r.u7[c] = __ldcs(&ub[127 + 32*c + lane]);
    #pragma unroll
    for (int c = 0; c < 2; c++) r.u6[c] = __ldcs(&ub[63 + 32*c + lane]);
    r.u5 = __ldcs(&ub[31 + lane]);
    r.uS = __ldcs(&ub[gs]);
}

__global__ void __launch_bounds__(NTHR, 5)
soft_tree_kernel(const float* __restrict__ x, const float* __restrict__ split_cond,
                 const float* __restrict__ u, const float* __restrict__ leaf_values,
                 const int* __restrict__ split_idx, float* __restrict__ out)
{
    // shared: x tile [RPB][NFEAT], then node const table, then leaf table
    extern __shared__ float smem[];
    float*  xs = smem;                                   // 32 KB
    float2* nc = (float2*)(smem + RPB * NFEAT);          // 256 * 8B  {scp, idx_bits}
    float2* lc = nc + 256;                               // 128 * 8B  {lf0, lfd}

    const unsigned FULL = 0xffffffffu;
    const float LOG2E = 1.4426950408889634f;
    const int tid  = threadIdx.x;
    const int lane = tid & 31;
    const int wid  = tid >> 5;
    const int warp_row0 = blockIdx.x * RPB + wid * RPW;
    float* xw = xs + (wid * RPW) * NFEAT;

    // build per-node constant tables (block-cooperative, once)
    for (int t = tid; t < NINT; t += NTHR)
        nc[t] = make_float2(split_cond[t] * LOG2E, __int_as_float(split_idx[t]));
    for (int t = tid; t < 128; t += NTHR) {
        float2 lf = reinterpret_cast<const float2*>(leaf_values)[t];
        lc[t] = make_float2(lf.x, lf.y - lf.x);
    }

    const int gs = (lane < 31) ? lane : 30;   // small-level node (lane31 dup, unused)
    const float2* ub0 = reinterpret_cast<const float2*>(u + (size_t)warp_row0 * (2*NINT));

    // prefetch u for row 0 BEFORE staging x, so both are in flight together
    URow cur;
    load_urow(cur, ub0, lane, gs);

    // stage this warp's RPW x-rows into shared (coalesced float4, streaming)
    {
        const float4* xg  = reinterpret_cast<const float4*>(x) + (size_t)warp_row0 * (NFEAT/4);
        float4*       xs4 = reinterpret_cast<float4*>(xw);
        #pragma unroll
        for (int i = 0; i < RPW*(NFEAT/4)/32; i++) xs4[i*32+lane] = __ldcs(&xg[i*32+lane]);
    }
    __syncthreads();   // tables + tiles visible

    float myres = 0.0f;

    #pragma unroll
    for (int i = 0; i < RPW; i++) {
        const float* xr = xw + i*NFEAT;

        // ---- issue next row's u loads before touching this row's data ----
        URow nxt;
        if (i + 1 < RPW)
            load_urow(nxt, ub0 + (size_t)(i+1)*NINT, lane, gs);

        // level 7: gate + fold leaves; lane holds v7 of local nodes 32c+lane
        float v7[4];
        #pragma unroll
        for (int c = 0; c < 4; c++) {
            float2 n  = nc[127 + 32*c + lane];
            float  xv = xr[__float_as_int(n.y)];
            float  w  = gate_w(cur.u7[c], xv, n.x);
            float2 lf = lc[32*c + lane];
            v7[c] = fmaf(w, lf.y, lf.x);
        }
        // level 6
        float v6[2];
        #pragma unroll
        for (int c = 0; c < 2; c++) {
            float2 n  = nc[63 + 32*c + lane];
            float  w  = gate_w(cur.u6[c], xr[__float_as_int(n.y)], n.x);
            float xa = __shfl_sync(FULL, v7[2*c],   2*lane);
            float xb = __shfl_sync(FULL, v7[2*c+1], 2*lane);
            float ya = __shfl_sync(FULL, v7[2*c],   2*lane+1);
            float yb = __shfl_sync(FULL, v7[2*c+1], 2*lane+1);
            float vL = (lane < 16) ? xa : xb;
            float vR = (lane < 16) ? ya : yb;
            v6[c] = fmaf(w, vR - vL, vL);
        }
        // level 5 (lane = node)
        float v5;
        {
            float2 n = nc[31 + lane];
            float  w = gate_w(cur.u5, xr[__float_as_int(n.y)], n.x);
            float xa = __shfl_sync(FULL, v6[0], 2*lane);
            float xb = __shfl_sync(FULL, v6[1], 2*lane);
            float ya = __shfl_sync(FULL, v6[0], 2*lane+1);
            float yb = __shfl_sync(FULL, v6[1], 2*lane+1);
            float vL = (lane < 16) ? xa : xb;
            float vR = (lane < 16) ? ya : yb;
            v5 = fmaf(w, vR - vL, vL);
        }
        // levels 4..0: all 31 gates in one warp-wide pass, fold by shuffle
        float ws;
        {
            float2 n = nc[gs];
            ws = gate_w(cur.uS, xr[__float_as_int(n.y)], n.x);  // lane k: node k (k<=30)
        }
        float vL = __shfl_sync(FULL, v5, 2*lane);
        float vR = __shfl_sync(FULL, v5, 2*lane+1);
        float v4 = fmaf(__shfl_sync(FULL, ws, 15+lane), vR-vL, vL);   // lanes<16
        vL = __shfl_sync(FULL, v4, 2*lane);
        vR = __shfl_sync(FULL, v4, 2*lane+1);
        float v3 = fmaf(__shfl_sync(FULL, ws, 7+lane), vR-vL, vL);    // lanes<8
        vL = __shfl_sync(FULL, v3, 2*lane);
        vR = __shfl_sync(FULL, v3, 2*lane+1);
        float v2 = fmaf(__shfl_sync(FULL, ws, 3+lane), vR-vL, vL);    // lanes<4
        vL = __shfl_sync(FULL, v2, 2*lane);
        vR = __shfl_sync(FULL, v2, 2*lane+1);
        float v1 = fmaf(__shfl_sync(FULL, ws, 1+lane), vR-vL, vL);    // lanes<2
        vL = __shfl_sync(FULL, v1, 0);
        vR = __shfl_sync(FULL, v1, 1);
        float v0 = fmaf(__shfl_sync(FULL, ws, 0), vR-vL, vL);         // all lanes equal

        if (lane == i) myres = v0;

        cur = nxt;   // rotate pipeline
    }

    if (lane < RPW) out[warp_row0 + lane] = myres;
}

extern "C" void kernel_launch(void* const* d_in, const int* in_sizes, int n_in,
                              void* d_out, int out_size)
{
    const float* x  = (const float*)d_in[0];
    const float* sc = (const float*)d_in[1];
    const float* u  = (const float*)d_in[2];
    const float* lv = (const float*)d_in[3];
    const int*   si = (const int*)d_in[4];
    float* out = (float*)d_out;

    const size_t smem = (size_t)RPB * NFEAT * sizeof(float)   // 32 KB x tile
                      + 256 * sizeof(float2)                  // node consts
                      + 128 * sizeof(float2);                 // leaf consts
    cudaFuncSetAttribute(soft_tree_kernel,
                         cudaFuncAttributeMaxDynamicSharedMemorySize, (int)smem);
    int blocks = out_size / RPB;                              // 262144/32 = 8192
    soft_tree_kernel<<<blocks, NTHR, smem>>>(x, sc, u, lv, si, out);
}